// round 7
// baseline (speedup 1.0000x reference)
#include <cuda_runtime.h>

// Problem constants
#define NB 8
#define NC 21
#define NW 512
#define NH 512
#define KK 5
#define KPAD 2
#define PLANE (NW * NH)

// 5-lane packing constants (6-bit lanes at bits 0,6,12,18,24; labels < 32)
#define LREP 0x01041041u   // 1 in each lane
#define CADD 0x1F7DF7DFu   // 31 in each lane
#define MBIT 0x20820820u   // bit5 of each lane

// Block: 128 threads, one row w, 4 contiguous h-pixels per thread (float4).
// Grid: (NW, NB). 12 blocks/SM resident (42-reg cap).
__global__ __launch_bounds__(128, 12)
void weight_matrix_kernel(const float* __restrict__ x,
                          const int*   __restrict__ y,
                          float*       __restrict__ out)
{
    // spack[i] = labels of rows w-2..w+2 at global col (i-2), packed into
    // 6-bit lanes (row r -> bits 6r). Cols outside [0,512) pack to 0 (Unfold
    // zero padding; lane 0 then mismatches any class c!=0, matching ref).
    __shared__ unsigned int spack[520];   // 2080 B

    const int w   = blockIdx.x;
    const int b   = blockIdx.y;
    const int tid = threadIdx.x;
    const int h0  = tid * 4;

    // ---- stage packed column words (5 coalesced row reads per entry) ----
    const int* yb = y + b * PLANE;
    for (int i = tid; i < 520; i += 128) {
        const int gc = i - KPAD;
        unsigned int pack = 0;
        if (gc >= 0 && gc < NH) {
            #pragma unroll
            for (int r = 0; r < KK; r++) {
                const int gr = w - KPAD + r;
                unsigned int v = 0;
                if (gr >= 0 && gr < NW) v = (unsigned)__ldg(&yb[gr * NH + gc]);
                pack |= v << (6 * r);
            }
        }
        spack[i] = pack;
    }
    __syncthreads();

    // ---- pull the count-phase smem words early (off the critical tail) ----
    const uint4 lo = *reinterpret_cast<const uint4*>(&spack[h0]);
    const uint4 hi = *reinterpret_cast<const uint4*>(&spack[h0 + 4]);

    // ---- argmax over 21 channels, load-ahead to keep LDGs in flight ----
    const float* xb = x + (size_t)(b * NC) * PLANE + w * NH + h0;
    float4 best = *reinterpret_cast<const float4*>(xb);
    float4 nxt  = *reinterpret_cast<const float4*>(xb + PLANE);
    int bc0 = 0, bc1 = 0, bc2 = 0, bc3 = 0;

    #pragma unroll 5
    for (int c = 1; c < NC; c++) {
        const float4 v = nxt;
        if (c + 1 < NC)
            nxt = *reinterpret_cast<const float4*>(xb + (c + 1) * PLANE);
        if (v.x > best.x) { best.x = v.x; bc0 = c; }
        if (v.y > best.y) { best.y = v.y; bc1 = c; }
        if (v.z > best.z) { best.z = v.z; bc2 = c; }
        if (v.w > best.w) { best.w = v.w; bc3 = c; }
    }

    // ---- 5x5 mismatch count via packed lanes ----
    const unsigned int w0 = lo.x, w1 = lo.y, w2 = lo.z, w3 = lo.w;
    const unsigned int w4 = hi.x, w5 = hi.y, w6 = hi.z, w7 = hi.w;

    const unsigned int r0 = (unsigned)bc0 * LREP;
    const unsigned int r1 = (unsigned)bc1 * LREP;
    const unsigned int r2 = (unsigned)bc2 * LREP;
    const unsigned int r3 = (unsigned)bc3 * LREP;

    // popc(((word ^ rep) + CADD) & MBIT) = # mismatching rows in that column
    #define CNT(wd, rp) __popc((((wd) ^ (rp)) + CADD) & MBIT)

    const int cnt0 = CNT(w0,r0)+CNT(w1,r0)+CNT(w2,r0)+CNT(w3,r0)+CNT(w4,r0);
    const int cnt1 = CNT(w1,r1)+CNT(w2,r1)+CNT(w3,r1)+CNT(w4,r1)+CNT(w5,r1);
    const int cnt2 = CNT(w2,r2)+CNT(w3,r2)+CNT(w4,r2)+CNT(w5,r2)+CNT(w6,r2);
    const int cnt3 = CNT(w3,r3)+CNT(w4,r3)+CNT(w5,r3)+CNT(w6,r3)+CNT(w7,r3);
    #undef CNT

    float4 o;
    o.x = 1.0f + 1.5f * (float)cnt0;
    o.y = 1.0f + 1.5f * (float)cnt1;
    o.z = 1.0f + 1.5f * (float)cnt2;
    o.w = 1.0f + 1.5f * (float)cnt3;

    *reinterpret_cast<float4*>(out + (b * NW + w) * NH + h0) = o;
}

extern "C" void kernel_launch(void* const* d_in, const int* in_sizes, int n_in,
                              void* d_out, int out_size)
{
    const float* x = (const float*)d_in[0];
    const int*   y = (const int*)d_in[1];
    float*       o = (float*)d_out;

    dim3 grid(NW, NB);
    weight_matrix_kernel<<<grid, 128>>>(x, y, o);
}

// round 8
// speedup vs baseline: 1.0539x; 1.0539x over previous
#include <cuda_runtime.h>

// Problem constants
#define NB 8
#define NC 21
#define NW 512
#define NH 512
#define KK 5
#define KPAD 2
#define PLANE (NW * NH)

// 5-lane packing constants (6-bit lanes at bits 0,6,12,18,24; labels < 32)
#define LREP 0x01041041u   // 1 in each lane
#define CADD 0x1F7DF7DFu   // 31 in each lane
#define MBIT 0x20820820u   // bit5 of each lane

// Block: 128 threads, one row w, 4 contiguous h-pixels per thread (float4).
// Grid: (NW, NB).
// Phase order: stage y (async-ish) -> argmax x-stream (hides staging) ->
// barrier (no-wait by then) -> packed count.
__global__ __launch_bounds__(128, 12)
void weight_matrix_kernel(const float* __restrict__ x,
                          const int*   __restrict__ y,
                          float*       __restrict__ out)
{
    // spack[i] = labels of rows w-2..w+2 at global col (i-2), packed into
    // 6-bit lanes (row r -> bits 6r). Cols outside [0,512) pack to 0 (Unfold
    // zero padding; lane 0 then mismatches any class c!=0, matching ref).
    __shared__ unsigned int spack[520];   // 2080 B

    const int w   = blockIdx.x;
    const int b   = blockIdx.y;
    const int tid = threadIdx.x;
    const int h0  = tid * 4;

    // ---- phase 1: stage packed column words (issue early, complete under
    //      the argmax stream) ----
    const int* yb = y + b * PLANE;
    for (int i = tid; i < 520; i += 128) {
        const int gc = i - KPAD;
        unsigned int pack = 0;
        if (gc >= 0 && gc < NH) {
            #pragma unroll
            for (int r = 0; r < KK; r++) {
                const int gr = w - KPAD + r;
                unsigned int v = 0;
                if (gr >= 0 && gr < NW) v = (unsigned)__ldg(&yb[gr * NH + gc]);
                pack |= v << (6 * r);
            }
        }
        spack[i] = pack;
    }

    // ---- phase 2: argmax over 21 channels (the DRAM stream; no barrier
    //      crossed yet, so it starts immediately at block launch) ----
    const float* xb = x + (size_t)(b * NC) * PLANE + w * NH + h0;
    float4 best = *reinterpret_cast<const float4*>(xb);
    int bc0 = 0, bc1 = 0, bc2 = 0, bc3 = 0;

    #pragma unroll 5
    for (int c = 1; c < NC; c++) {
        const float4 v = *reinterpret_cast<const float4*>(xb + c * PLANE);
        if (v.x > best.x) { best.x = v.x; bc0 = c; }
        if (v.y > best.y) { best.y = v.y; bc1 = c; }
        if (v.z > best.z) { best.z = v.z; bc2 = c; }
        if (v.w > best.w) { best.w = v.w; bc3 = c; }
    }

    // ---- barrier: staging finished long ago; near-zero wait ----
    __syncthreads();

    // ---- phase 3: 5x5 mismatch count via packed lanes ----
    // Pixel p (global col h0+p) needs stored cols (h0+p)..(h0+p+4).
    // Thread window = spack[h0 .. h0+8) : two aligned int4 loads.
    const uint4 lo = *reinterpret_cast<const uint4*>(&spack[h0]);
    const uint4 hi = *reinterpret_cast<const uint4*>(&spack[h0 + 4]);
    const unsigned int w0 = lo.x, w1 = lo.y, w2 = lo.z, w3 = lo.w;
    const unsigned int w4 = hi.x, w5 = hi.y, w6 = hi.z, w7 = hi.w;

    const unsigned int r0 = (unsigned)bc0 * LREP;
    const unsigned int r1 = (unsigned)bc1 * LREP;
    const unsigned int r2 = (unsigned)bc2 * LREP;
    const unsigned int r3 = (unsigned)bc3 * LREP;

    // popc(((word ^ rep) + CADD) & MBIT) = # mismatching rows in that column
    #define CNT(wd, rp) __popc((((wd) ^ (rp)) + CADD) & MBIT)

    const int cnt0 = CNT(w0,r0)+CNT(w1,r0)+CNT(w2,r0)+CNT(w3,r0)+CNT(w4,r0);
    const int cnt1 = CNT(w1,r1)+CNT(w2,r1)+CNT(w3,r1)+CNT(w4,r1)+CNT(w5,r1);
    const int cnt2 = CNT(w2,r2)+CNT(w3,r2)+CNT(w4,r2)+CNT(w5,r2)+CNT(w6,r2);
    const int cnt3 = CNT(w3,r3)+CNT(w4,r3)+CNT(w5,r3)+CNT(w6,r3)+CNT(w7,r3);
    #undef CNT

    float4 o;
    o.x = 1.0f + 1.5f * (float)cnt0;
    o.y = 1.0f + 1.5f * (float)cnt1;
    o.z = 1.0f + 1.5f * (float)cnt2;
    o.w = 1.0f + 1.5f * (float)cnt3;

    *reinterpret_cast<float4*>(out + (b * NW + w) * NH + h0) = o;
}

extern "C" void kernel_launch(void* const* d_in, const int* in_sizes, int n_in,
                              void* d_out, int out_size)
{
    const float* x = (const float*)d_in[0];
    const int*   y = (const int*)d_in[1];
    float*       o = (float*)d_out;

    dim3 grid(NW, NB);
    weight_matrix_kernel<<<grid, 128>>>(x, y, o);
}